// round 6
// baseline (speedup 1.0000x reference)
#include <cuda_runtime.h>
#include <cooperative_groups.h>
#include <math.h>
#include <stdint.h>

namespace cg = cooperative_groups;

#define BB  64
#define HH  512
#define LL  128
#define G4H 2048   // 4*H
#define CR  8      // CTAs per cluster
#define BPC 4      // batches per cluster
#define NT  256    // threads per CTA
#define NW  8      // warps per CTA

// Dynamic SMEM layout (float offsets)
#define OFF_CTX 0                      // [256][128]  own ctx half (persistent)
#define OFF_H   (OFF_CTX + 256*LL)     // [BPC][HH]   h of 4 batches
#define OFF_X   (OFF_H   + BPC*HH)     // [BPC][2HH]  [hid | h_t] of 4 batches
#define OFF_G   (OFF_X   + BPC*2*HH)   // [G4H]       own gates
#define OFF_INP (OFF_G   + G4H)        // [HH]        own attn proj
#define OFF_C   (OFF_INP + HH)         // [HH/2]      own c slice
#define OFF_V   (OFF_C   + HH/2)       // [HH]
#define OFF_PL  (OFF_V   + HH)         // [2][LL]     local partials
#define OFF_PR  (OFF_PL  + 2*LL)       // [2][LL]     pair partials
#define OFF_AL  (OFF_PR  + 2*LL)       // [LL]        alpha
#define OFF_MK  (OFF_AL  + LL)         // [LL]        mask
#define SMEM_FLOATS (OFF_MK + LL)
#define SMEM_BYTES  (SMEM_FLOATS * 4)  // 172,032 B

// Precomputed context projection: ctx[b,h,l] = sum_d W_ctx[h,d]*context[b,d,l] + b_ctx[h]
__device__ float g_ctx[(size_t)BB * HH * LL];   // 16 MB module-static scratch

// ---------------------------------------------------------------------------
// Kernel 1: ctx precompute.  grid (B, H/64), block 128 (l).
// ---------------------------------------------------------------------------
__global__ __launch_bounds__(128)
void ctx_precompute_kernel(const float* __restrict__ context,
                           const float* __restrict__ Wctx,
                           const float* __restrict__ bctx)
{
    const int b  = blockIdx.x;
    const int ht = blockIdx.y;
    const int l  = threadIdx.x;

    __shared__ __align__(16) float sWT[32][64];

    float acc[64];
#pragma unroll
    for (int i = 0; i < 64; i++) acc[i] = 0.f;

    const float* X = context + (size_t)b * HH * LL;

    for (int d0 = 0; d0 < HH; d0 += 32) {
        __syncthreads();
        for (int i = threadIdx.x; i < 64 * 32; i += 128) {
            int hh = i >> 5, dd = i & 31;
            sWT[dd][hh] = Wctx[(size_t)(ht * 64 + hh) * HH + d0 + dd];
        }
        __syncthreads();
#pragma unroll 4
        for (int dd = 0; dd < 32; dd++) {
            float x = X[(size_t)(d0 + dd) * LL + l];
            const float4* w4 = (const float4*)(&sWT[dd][0]);
#pragma unroll
            for (int j = 0; j < 16; j++) {
                float4 w = w4[j];
                acc[4*j + 0] += w.x * x;
                acc[4*j + 1] += w.y * x;
                acc[4*j + 2] += w.z * x;
                acc[4*j + 3] += w.w * x;
            }
        }
    }

    float* dst = g_ctx + (size_t)b * HH * LL;
#pragma unroll
    for (int hh = 0; hh < 64; hh++) {
        int h = ht * 64 + hh;
        dst[(size_t)h * LL + l] = acc[hh] + bctx[h];
    }
}

// ---------------------------------------------------------------------------
// Kernel 2: 128-step recurrence.  128 CTAs in 16 clusters of 8.
// Cluster serves 4 batches; batch j owned by CTA pair (rank 2j = h-half 0,
// rank 2j+1 = h-half 1).  Shared GEMVs row-sliced by rank; own ctx half is
// pinned in SMEM for the whole kernel (immune to cluster.sync L1 flushes).
// ---------------------------------------------------------------------------
__device__ __forceinline__ float warp_sum(float v) {
#pragma unroll
    for (int o = 16; o > 0; o >>= 1) v += __shfl_xor_sync(0xffffffffu, v, o);
    return v;
}
__device__ __forceinline__ float sigf(float x) { return 1.0f / (1.0f + expf(-x)); }

__global__ __launch_bounds__(NT, 1) __cluster_dims__(CR, 1, 1)
void ptrnet_kernel(const float* __restrict__ h0,
                   const float* __restrict__ c0,
                   const float* __restrict__ Whh, const float* __restrict__ bhh,
                   const float* __restrict__ Win, const float* __restrict__ bin,
                   const float* __restrict__ V,
                   const float* __restrict__ Wout, const float* __restrict__ bout,
                   float* __restrict__ out)
{
    extern __shared__ __align__(16) float smf[];
    float* sctx   = smf + OFF_CTX;   // [256][LL] own h-half of ctx
    float* shAll  = smf + OFF_H;     // [BPC][HH]
    float* sxAll  = smf + OFF_X;     // [BPC][2*HH]
    float* sgates = smf + OFF_G;     // [G4H]
    float* sinp   = smf + OFF_INP;   // [HH]
    float* sc     = smf + OFF_C;     // [HH/2]
    float* sV     = smf + OFF_V;     // [HH]
    float* spartL = smf + OFF_PL;    // [2][LL]
    float* sPair  = smf + OFF_PR;    // [2][LL]
    float* salpha = smf + OFF_AL;    // [LL]
    float* smask  = smf + OFF_MK;    // [LL]

    cg::cluster_group cluster = cg::this_cluster();
    const int rank = (int)cluster.block_rank();   // 0..7
    const int jown = rank >> 1;                   // batch-in-cluster this CTA co-owns
    const int half = rank & 1;                    // h-half: [half*256, half*256+256)
    const int clu  = blockIdx.x / CR;
    const int b0   = clu * BPC;
    const int b    = b0 + jown;
    const int tid  = threadIdx.x;
    const int lane = tid & 31;
    const int warp = tid >> 5;

    // ---- init ----
#pragma unroll
    for (int j = 0; j < BPC; j++)
        for (int i = tid; i < HH; i += NT)
            shAll[j * HH + i] = h0[(size_t)(b0 + j) * HH + i];
    sc[tid] = c0[(size_t)b * HH + half * 256 + tid];
    for (int i = tid; i < HH; i += NT) sV[i] = V[i];
    if (tid < LL) smask[tid] = 1.0f;
    // pin own ctx half in SMEM (256 rows x 128)
    {
        const float4* src = (const float4*)(g_ctx + (size_t)b * HH * LL
                                            + (size_t)(half * 256) * LL);
        float4* dst = (float4*)sctx;
        for (int i = tid; i < 256 * LL / 4; i += NT) dst[i] = src[i];
    }
    __syncthreads();

    float* out_alpha = out + (size_t)b * LL * LL;
    float* out_ptr   = out + (size_t)BB * LL * LL + (size_t)b * LL;

    for (int step = 0; step < LL; step++) {
        // ---- phase 1: gates.  rank computes Whh rows [rank*256,+256) for all
        //      4 batches; consumer h-half is (rank&1) -> scatter to 4 CTAs. ----
        {
            float4 hreg[BPC][4];
#pragma unroll
            for (int j = 0; j < BPC; j++) {
                const float4* h4 = (const float4*)(shAll + j * HH);
#pragma unroll
                for (int t = 0; t < 4; t++) hreg[j][t] = h4[t * 32 + lane];
            }
            const int hd = rank & 1;
            for (int rr = warp; rr < 256; rr += NW) {
                const int row = rank * 256 + rr;
                const float4* wrow = (const float4*)(Whh + (size_t)row * HH);
                float a[BPC] = {0.f, 0.f, 0.f, 0.f};
#pragma unroll
                for (int t = 0; t < 4; t++) {
                    float4 w = wrow[t * 32 + lane];
#pragma unroll
                    for (int j = 0; j < BPC; j++)
                        a[j] += w.x * hreg[j][t].x + w.y * hreg[j][t].y
                              + w.z * hreg[j][t].z + w.w * hreg[j][t].w;
                }
#pragma unroll
                for (int j = 0; j < BPC; j++) a[j] = warp_sum(a[j]);
                float bb = bhh[row];
                if (lane < BPC) {   // lane = batch j; dst rank = 2j + hd
                    float* g = (float*)cluster.map_shared_rank(sgates, 2 * lane + hd);
                    g[row] = a[lane] + bb;
                }
            }
        }
        cluster.sync();

        // ---- phase 2: LSTM pointwise on own (batch, h-half); broadcast h_t
        //      to every CTA's sxAll[jown][HH + h]. ----
        {
            int h = half * 256 + tid;
            float ig = sgates[h];
            float fg = sgates[HH + h];
            float gg = sgates[2 * HH + h];
            float og = sgates[3 * HH + h];
            float ct = sigf(fg) * sc[tid] + sigf(ig) * tanhf(gg);
            float ht = sigf(og) * tanhf(ct);
            sc[tid] = ct;
#pragma unroll
            for (int k = 0; k < CR; k++) {
                float* x = (float*)cluster.map_shared_rank(sxAll, k);
                x[jown * 2 * HH + HH + h] = ht;
            }
        }
        cluster.sync();

        // ---- phase 3: inp.  rank computes Win rows [rank*64,+64); consumer
        //      h-half is (rank>>2). ----
        {
            float4 xreg[BPC][4];
#pragma unroll
            for (int j = 0; j < BPC; j++) {
                const float4* x4 = (const float4*)(sxAll + j * 2 * HH + HH);
#pragma unroll
                for (int t = 0; t < 4; t++) xreg[j][t] = x4[t * 32 + lane];
            }
            const int hd = (rank >> 2) & 1;
            for (int rr = warp; rr < 64; rr += NW) {
                const int row = rank * 64 + rr;
                const float4* wrow = (const float4*)(Win + (size_t)row * HH);
                float a[BPC] = {0.f, 0.f, 0.f, 0.f};
#pragma unroll
                for (int t = 0; t < 4; t++) {
                    float4 w = wrow[t * 32 + lane];
#pragma unroll
                    for (int j = 0; j < BPC; j++)
                        a[j] += w.x * xreg[j][t].x + w.y * xreg[j][t].y
                              + w.z * xreg[j][t].z + w.w * xreg[j][t].w;
                }
#pragma unroll
                for (int j = 0; j < BPC; j++) a[j] = warp_sum(a[j]);
                float bb = bin[row];
                if (lane < BPC) {
                    float* p = (float*)cluster.map_shared_rank(sinp, 2 * lane + hd);
                    p[row] = a[lane] + bb;
                }
            }
        }
        cluster.sync();

        // ---- phase 4: score partials over own h-half (ctx from SMEM);
        //      send combined partial to BOTH pair CTAs. ----
        {
            const int hc = warp >> 2;                  // 0..1 (128 h each)
            const int lg = warp & 3;                   // 0..3 (32 l each)
            const int l  = lg * 32 + lane;
            const int hgl = half * 256 + hc * 128;     // global h base
            const float* cl = sctx + (size_t)(hc * 128) * LL + l;
            float acc = 0.f;
#pragma unroll 4
            for (int hh = 0; hh < 128; hh++)
                acc += sV[hgl + hh] * tanhf(sinp[hgl + hh] + cl[(size_t)hh * LL]);
            spartL[hc * LL + l] = acc;
        }
        __syncthreads();
        if (tid < LL) {
            float tot = spartL[tid] + spartL[LL + tid];
            float* pA = (float*)cluster.map_shared_rank(sPair, rank & ~1);
            float* pB = (float*)cluster.map_shared_rank(sPair, rank | 1);
            pA[half * LL + tid] = tot;
            pB[half * LL + tid] = tot;
        }
        cluster.sync();

        // ---- phase 5: masked softmax + argmax + mask update, computed
        //      REDUNDANTLY on both pair CTAs (deterministic -> identical).
        //      Only half==0 writes gmem. ----
        if (warp == 0) {
            float sv[4];
            float mx = -INFINITY;
#pragma unroll
            for (int k = 0; k < 4; k++) {
                int l = lane + 32 * k;
                float s = sPair[l] + sPair[LL + l];
                bool m = (smask[l] != 0.f);
                sv[k] = m ? s : -INFINITY;
                mx = fmaxf(mx, sv[k]);
            }
#pragma unroll
            for (int o = 16; o > 0; o >>= 1)
                mx = fmaxf(mx, __shfl_xor_sync(0xffffffffu, mx, o));

            float es[4], sum = 0.f;
#pragma unroll
            for (int k = 0; k < 4; k++) {
                es[k] = (sv[k] == -INFINITY) ? 0.f : expf(sv[k] - mx);
                sum += es[k];
            }
            sum = warp_sum(sum);

            float bestv = -1.f;
            int   besti = LL;
#pragma unroll
            for (int k = 0; k < 4; k++) {
                int l = lane + 32 * k;
                float a = es[k] / sum;
                salpha[l] = a;
                if (half == 0) out_alpha[(size_t)step * LL + l] = a;
                if (a > bestv) { bestv = a; besti = l; }
            }
#pragma unroll
            for (int o = 16; o > 0; o >>= 1) {
                float ov = __shfl_xor_sync(0xffffffffu, bestv, o);
                int   oi = __shfl_xor_sync(0xffffffffu, besti, o);
                if (ov > bestv || (ov == bestv && oi < besti)) { bestv = ov; besti = oi; }
            }
            if (lane == 0) {
                smask[besti] = 0.f;
                if (half == 0) out_ptr[step] = (float)besti;
            }
        }
        __syncthreads();

        // ---- phase 6: hid over own h-half (ctx from SMEM); broadcast to
        //      every CTA's sxAll[jown][h]. ----
        {
            const float4 a4 = ((const float4*)salpha)[lane];
            for (int rr = warp; rr < 256; rr += NW) {
                const float4 cv = ((const float4*)(sctx + (size_t)rr * LL))[lane];
                float acc = cv.x * a4.x + cv.y * a4.y + cv.z * a4.z + cv.w * a4.w;
                acc = warp_sum(acc);
                const int h = half * 256 + rr;
                if (lane < CR) {
                    float* x = (float*)cluster.map_shared_rank(sxAll, lane);
                    x[jown * 2 * HH + h] = acc;
                }
            }
        }
        cluster.sync();

        // ---- phase 7: h_new.  rank computes Wout rows [rank*64,+64) for all
        //      4 batches; broadcast every value to all 8 CTAs' shAll[j][row]. ----
        {
            for (int rr = warp; rr < 64; rr += NW) {
                const int row = rank * 64 + rr;
                const float4* wrow = (const float4*)(Wout + (size_t)row * 2 * HH);
                float a[BPC] = {0.f, 0.f, 0.f, 0.f};
#pragma unroll
                for (int t = 0; t < 8; t++) {
                    float4 w = wrow[t * 32 + lane];
#pragma unroll
                    for (int j = 0; j < BPC; j++) {
                        float4 x = ((const float4*)(sxAll + j * 2 * HH))[t * 32 + lane];
                        a[j] += w.x * x.x + w.y * x.y + w.z * x.z + w.w * x.w;
                    }
                }
#pragma unroll
                for (int j = 0; j < BPC; j++) a[j] = warp_sum(a[j]);
                float bb = bout[row];
                {   // 32 lanes = 4 batches x 8 dst ranks, one store each
                    int j   = lane >> 3;      // 0..3
                    int dst = lane & 7;       // 0..7
                    float v = tanhf(a[j] + bb);
                    float* hdst = (float*)cluster.map_shared_rank(shAll, dst);
                    hdst[j * HH + row] = v;
                }
            }
        }
        cluster.sync();
    }

    // ---- final h_f, c_f ----
    float* out_hf = out + (size_t)BB * LL * LL + (size_t)BB * LL;
    float* out_cf = out_hf + (size_t)BB * HH;
    if (half == 0)
        for (int i = tid; i < HH; i += NT)
            out_hf[(size_t)b * HH + i] = shAll[jown * HH + i];
    out_cf[(size_t)b * HH + half * 256 + tid] = sc[tid];
}

// ---------------------------------------------------------------------------
// Launcher.  Input order (metadata):
//  0 embedded_inputs (unused)  1 decoder_input (unused)
//  2 h0  3 c0  4 context  5 W_hh  6 b_hh  7 W_in  8 b_in
//  9 W_ctx  10 b_ctx  11 V  12 W_out  13 b_out
// Output: concat of outputs[B,L,L], pointers[B,L], h_f[B,H], c_f[B,H] (f32)
// ---------------------------------------------------------------------------
extern "C" void kernel_launch(void* const* d_in, const int* in_sizes, int n_in,
                              void* d_out, int out_size)
{
    (void)in_sizes; (void)n_in; (void)out_size;
    const float* h0      = (const float*)d_in[2];
    const float* c0      = (const float*)d_in[3];
    const float* context = (const float*)d_in[4];
    const float* Whh     = (const float*)d_in[5];
    const float* bhh     = (const float*)d_in[6];
    const float* Win     = (const float*)d_in[7];
    const float* bin     = (const float*)d_in[8];
    const float* Wctx    = (const float*)d_in[9];
    const float* bctx    = (const float*)d_in[10];
    const float* V       = (const float*)d_in[11];
    const float* Wout    = (const float*)d_in[12];
    const float* bout    = (const float*)d_in[13];
    float* out = (float*)d_out;

    cudaFuncSetAttribute(ptrnet_kernel,
                         cudaFuncAttributeMaxDynamicSharedMemorySize, SMEM_BYTES);

    ctx_precompute_kernel<<<dim3(BB, HH / 64), 128>>>(context, Wctx, bctx);
    ptrnet_kernel<<<BB * 2, NT, SMEM_BYTES>>>(h0, c0, Whh, bhh, Win, bin, V,
                                              Wout, bout, out);
}

// round 7
// speedup vs baseline: 1.1137x; 1.1137x over previous
#include <cuda_runtime.h>
#include <cooperative_groups.h>
#include <math.h>
#include <stdint.h>

namespace cg = cooperative_groups;

#define BB  64
#define HH  512
#define LL  128
#define G4H 2048   // 4*H
#define CR  8      // CTAs per cluster
#define BPC 4      // batches per cluster
#define NT  512    // threads per CTA
#define NW  16     // warps per CTA

// Dynamic SMEM layout (float offsets)
#define OFF_CTX 0                      // [256][128]  own ctx half (persistent)
#define OFF_H   (OFF_CTX + 256*LL)     // [BPC][HH]   h of 4 batches
#define OFF_X   (OFF_H   + BPC*HH)     // [BPC][2HH]  [hid | h_t] of 4 batches
#define OFF_G   (OFF_X   + BPC*2*HH)   // [G4H]       own gates
#define OFF_INP (OFF_G   + G4H)        // [HH]        own attn proj
#define OFF_C   (OFF_INP + HH)         // [HH/2]      own c slice
#define OFF_V   (OFF_C   + HH/2)       // [HH]
#define OFF_PL  (OFF_V   + HH)         // [4][LL]     local partials
#define OFF_PR  (OFF_PL  + 4*LL)       // [2][LL]     pair partials
#define OFF_AL  (OFF_PR  + 2*LL)       // [LL]        alpha
#define OFF_MK  (OFF_AL  + LL)         // [LL]        mask
#define SMEM_FLOATS (OFF_MK + LL)
#define SMEM_BYTES  (SMEM_FLOATS * 4)  // 173,056 B

// Precomputed context projection: ctx[b,h,l] = sum_d W_ctx[h,d]*context[b,d,l] + b_ctx[h]
__device__ float g_ctx[(size_t)BB * HH * LL];   // 16 MB module-static scratch

// ---------------------------------------------------------------------------
// Kernel 1: ctx precompute.  grid (B, H/64), block 128 (l).
// ---------------------------------------------------------------------------
__global__ __launch_bounds__(128)
void ctx_precompute_kernel(const float* __restrict__ context,
                           const float* __restrict__ Wctx,
                           const float* __restrict__ bctx)
{
    const int b  = blockIdx.x;
    const int ht = blockIdx.y;
    const int l  = threadIdx.x;

    __shared__ __align__(16) float sWT[32][64];

    float acc[64];
#pragma unroll
    for (int i = 0; i < 64; i++) acc[i] = 0.f;

    const float* X = context + (size_t)b * HH * LL;

    for (int d0 = 0; d0 < HH; d0 += 32) {
        __syncthreads();
        for (int i = threadIdx.x; i < 64 * 32; i += 128) {
            int hh = i >> 5, dd = i & 31;
            sWT[dd][hh] = Wctx[(size_t)(ht * 64 + hh) * HH + d0 + dd];
        }
        __syncthreads();
#pragma unroll 4
        for (int dd = 0; dd < 32; dd++) {
            float x = X[(size_t)(d0 + dd) * LL + l];
            const float4* w4 = (const float4*)(&sWT[dd][0]);
#pragma unroll
            for (int j = 0; j < 16; j++) {
                float4 w = w4[j];
                acc[4*j + 0] += w.x * x;
                acc[4*j + 1] += w.y * x;
                acc[4*j + 2] += w.z * x;
                acc[4*j + 3] += w.w * x;
            }
        }
    }

    float* dst = g_ctx + (size_t)b * HH * LL;
#pragma unroll
    for (int hh = 0; hh < 64; hh++) {
        int h = ht * 64 + hh;
        dst[(size_t)h * LL + l] = acc[hh] + bctx[h];
    }
}

// ---------------------------------------------------------------------------
// Fast transcendentals (MUFU-based, abs err ~1e-7; clamped for safety).
// ---------------------------------------------------------------------------
__device__ __forceinline__ float ftanh(float x) {
    float xc = fminf(fmaxf(x, -15.f), 15.f);
    float e  = __expf(2.f * xc);
    return __fdividef(e - 1.f, e + 1.f);
}
__device__ __forceinline__ float fsig(float x) {
    float xc = fminf(fmaxf(x, -30.f), 30.f);
    return __fdividef(1.f, 1.f + __expf(-xc));
}
__device__ __forceinline__ float warp_sum(float v) {
#pragma unroll
    for (int o = 16; o > 0; o >>= 1) v += __shfl_xor_sync(0xffffffffu, v, o);
    return v;
}

// ---------------------------------------------------------------------------
// Kernel 2: 128-step recurrence.  128 CTAs in 16 clusters of 8.
// Cluster serves 4 batches; batch j owned by CTA pair (rank 2j = h-half 0,
// rank 2j+1 = h-half 1).  Shared GEMVs row-sliced by rank; own ctx half is
// pinned in SMEM.  512 threads/CTA for latency hiding.
// ---------------------------------------------------------------------------
__global__ __launch_bounds__(NT, 1) __cluster_dims__(CR, 1, 1)
void ptrnet_kernel(const float* __restrict__ h0,
                   const float* __restrict__ c0,
                   const float* __restrict__ Whh, const float* __restrict__ bhh,
                   const float* __restrict__ Win, const float* __restrict__ bin,
                   const float* __restrict__ V,
                   const float* __restrict__ Wout, const float* __restrict__ bout,
                   float* __restrict__ out)
{
    extern __shared__ __align__(16) float smf[];
    float* sctx   = smf + OFF_CTX;   // [256][LL] own h-half of ctx
    float* shAll  = smf + OFF_H;     // [BPC][HH]
    float* sxAll  = smf + OFF_X;     // [BPC][2*HH]
    float* sgates = smf + OFF_G;     // [G4H]
    float* sinp   = smf + OFF_INP;   // [HH]
    float* sc     = smf + OFF_C;     // [HH/2]
    float* sV     = smf + OFF_V;     // [HH]
    float* spartL = smf + OFF_PL;    // [4][LL]
    float* sPair  = smf + OFF_PR;    // [2][LL]
    float* salpha = smf + OFF_AL;    // [LL]
    float* smask  = smf + OFF_MK;    // [LL]

    cg::cluster_group cluster = cg::this_cluster();
    const int rank = (int)cluster.block_rank();   // 0..7
    const int jown = rank >> 1;                   // batch-in-cluster this CTA co-owns
    const int half = rank & 1;                    // h-half: [half*256, half*256+256)
    const int clu  = blockIdx.x / CR;
    const int b0   = clu * BPC;
    const int b    = b0 + jown;
    const int tid  = threadIdx.x;
    const int lane = tid & 31;
    const int warp = tid >> 5;

    // ---- init ----
#pragma unroll
    for (int j = 0; j < BPC; j++)
        for (int i = tid; i < HH; i += NT)
            shAll[j * HH + i] = h0[(size_t)(b0 + j) * HH + i];
    if (tid < 256) sc[tid] = c0[(size_t)b * HH + half * 256 + tid];
    for (int i = tid; i < HH; i += NT) sV[i] = V[i];
    if (tid < LL) smask[tid] = 1.0f;
    {   // pin own ctx half in SMEM (256 rows x 128)
        const float4* src = (const float4*)(g_ctx + (size_t)b * HH * LL
                                            + (size_t)(half * 256) * LL);
        float4* dst = (float4*)sctx;
        for (int i = tid; i < 256 * LL / 4; i += NT) dst[i] = src[i];
    }
    __syncthreads();

    float* out_alpha = out + (size_t)b * LL * LL;
    float* out_ptr   = out + (size_t)BB * LL * LL + (size_t)b * LL;

    for (int step = 0; step < LL; step++) {
        // ---- phase 1: gates.  rank computes Whh rows [rank*256,+256) for all
        //      4 batches; consumer h-half is (rank&1) -> scatter to 4 CTAs. ----
        {
            const int hd = rank & 1;
#pragma unroll 2
            for (int rr = warp; rr < 256; rr += NW) {
                const int row = rank * 256 + rr;
                const float4* wrow = (const float4*)(Whh + (size_t)row * HH);
                float a0 = 0.f, a1 = 0.f, a2 = 0.f, a3 = 0.f;
#pragma unroll
                for (int t = 0; t < 4; t++) {
                    float4 w  = wrow[t * 32 + lane];
                    float4 x0 = ((const float4*)(shAll + 0 * HH))[t * 32 + lane];
                    float4 x1 = ((const float4*)(shAll + 1 * HH))[t * 32 + lane];
                    float4 x2 = ((const float4*)(shAll + 2 * HH))[t * 32 + lane];
                    float4 x3 = ((const float4*)(shAll + 3 * HH))[t * 32 + lane];
                    a0 += w.x*x0.x + w.y*x0.y + w.z*x0.z + w.w*x0.w;
                    a1 += w.x*x1.x + w.y*x1.y + w.z*x1.z + w.w*x1.w;
                    a2 += w.x*x2.x + w.y*x2.y + w.z*x2.z + w.w*x2.w;
                    a3 += w.x*x3.x + w.y*x3.y + w.z*x3.z + w.w*x3.w;
                }
                a0 = warp_sum(a0); a1 = warp_sum(a1);
                a2 = warp_sum(a2); a3 = warp_sum(a3);
                float bb = bhh[row];
                if (lane < BPC) {   // lane = batch j; dst rank = 2j + hd
                    float av = (lane == 0) ? a0 : (lane == 1) ? a1
                             : (lane == 2) ? a2 : a3;
                    float* g = (float*)cluster.map_shared_rank(sgates, 2 * lane + hd);
                    g[row] = av + bb;
                }
            }
        }
        cluster.sync();

        // ---- phase 2: LSTM pointwise on own (batch, h-half); broadcast h_t
        //      to every CTA's sxAll[jown][HH + h]. ----
        if (tid < 256) {
            int h = half * 256 + tid;
            float ig = sgates[h];
            float fg = sgates[HH + h];
            float gg = sgates[2 * HH + h];
            float og = sgates[3 * HH + h];
            float ct = fsig(fg) * sc[tid] + fsig(ig) * ftanh(gg);
            float ht = fsig(og) * ftanh(ct);
            sc[tid] = ct;
#pragma unroll
            for (int k = 0; k < CR; k++) {
                float* x = (float*)cluster.map_shared_rank(sxAll, k);
                x[jown * 2 * HH + HH + h] = ht;
            }
        }
        cluster.sync();

        // ---- phase 3: inp.  rank computes Win rows [rank*64,+64); consumer
        //      h-half is (rank>>2). ----
        {
            const int hd = (rank >> 2) & 1;
#pragma unroll 2
            for (int rr = warp; rr < 64; rr += NW) {
                const int row = rank * 64 + rr;
                const float4* wrow = (const float4*)(Win + (size_t)row * HH);
                float a0 = 0.f, a1 = 0.f, a2 = 0.f, a3 = 0.f;
#pragma unroll
                for (int t = 0; t < 4; t++) {
                    float4 w  = wrow[t * 32 + lane];
                    float4 x0 = ((const float4*)(sxAll + 0*2*HH + HH))[t * 32 + lane];
                    float4 x1 = ((const float4*)(sxAll + 1*2*HH + HH))[t * 32 + lane];
                    float4 x2 = ((const float4*)(sxAll + 2*2*HH + HH))[t * 32 + lane];
                    float4 x3 = ((const float4*)(sxAll + 3*2*HH + HH))[t * 32 + lane];
                    a0 += w.x*x0.x + w.y*x0.y + w.z*x0.z + w.w*x0.w;
                    a1 += w.x*x1.x + w.y*x1.y + w.z*x1.z + w.w*x1.w;
                    a2 += w.x*x2.x + w.y*x2.y + w.z*x2.z + w.w*x2.w;
                    a3 += w.x*x3.x + w.y*x3.y + w.z*x3.z + w.w*x3.w;
                }
                a0 = warp_sum(a0); a1 = warp_sum(a1);
                a2 = warp_sum(a2); a3 = warp_sum(a3);
                float bb = bin[row];
                if (lane < BPC) {
                    float av = (lane == 0) ? a0 : (lane == 1) ? a1
                             : (lane == 2) ? a2 : a3;
                    float* p = (float*)cluster.map_shared_rank(sinp, 2 * lane + hd);
                    p[row] = av + bb;
                }
            }
        }
        cluster.sync();

        // ---- phase 4: score partials over own h-half (ctx from SMEM, fast
        //      tanh); 16 warps = 4 h-chunks x 4 l-groups. ----
        {
            const int hc = warp >> 2;                  // 0..3 (64 h each)
            const int lg = warp & 3;                   // 0..3 (32 l each)
            const int l  = lg * 32 + lane;
            const int hloc = hc * 64;                  // local h base in [0,256)
            const int hgl  = half * 256 + hloc;        // global h base
            const float* cl = sctx + (size_t)hloc * LL + l;
            float acc = 0.f;
#pragma unroll 4
            for (int hh = 0; hh < 64; hh++)
                acc += sV[hgl + hh] * ftanh(sinp[hgl + hh] + cl[(size_t)hh * LL]);
            spartL[hc * LL + l] = acc;
        }
        __syncthreads();
        if (tid < LL) {
            float tot = spartL[tid] + spartL[LL + tid]
                      + spartL[2 * LL + tid] + spartL[3 * LL + tid];
            float* pA = (float*)cluster.map_shared_rank(sPair, rank & ~1);
            float* pB = (float*)cluster.map_shared_rank(sPair, rank | 1);
            pA[half * LL + tid] = tot;
            pB[half * LL + tid] = tot;
        }
        cluster.sync();

        // ---- phase 5: masked softmax + argmax + mask update, computed
        //      REDUNDANTLY on both pair CTAs (deterministic -> identical).
        //      Only half==0 writes gmem. ----
        if (warp == 0) {
            float sv[4];
            float mx = -INFINITY;
#pragma unroll
            for (int k = 0; k < 4; k++) {
                int l = lane + 32 * k;
                float s = sPair[l] + sPair[LL + l];
                bool m = (smask[l] != 0.f);
                sv[k] = m ? s : -INFINITY;
                mx = fmaxf(mx, sv[k]);
            }
#pragma unroll
            for (int o = 16; o > 0; o >>= 1)
                mx = fmaxf(mx, __shfl_xor_sync(0xffffffffu, mx, o));

            float es[4], sum = 0.f;
#pragma unroll
            for (int k = 0; k < 4; k++) {
                es[k] = (sv[k] == -INFINITY) ? 0.f : __expf(sv[k] - mx);
                sum += es[k];
            }
            sum = warp_sum(sum);

            float inv = __fdividef(1.f, sum);
            float bestv = -1.f;
            int   besti = LL;
#pragma unroll
            for (int k = 0; k < 4; k++) {
                int l = lane + 32 * k;
                float a = es[k] * inv;
                salpha[l] = a;
                if (half == 0) out_alpha[(size_t)step * LL + l] = a;
                if (a > bestv) { bestv = a; besti = l; }
            }
#pragma unroll
            for (int o = 16; o > 0; o >>= 1) {
                float ov = __shfl_xor_sync(0xffffffffu, bestv, o);
                int   oi = __shfl_xor_sync(0xffffffffu, besti, o);
                if (ov > bestv || (ov == bestv && oi < besti)) { bestv = ov; besti = oi; }
            }
            if (lane == 0) {
                smask[besti] = 0.f;
                if (half == 0) out_ptr[step] = (float)besti;
            }
        }
        __syncthreads();

        // ---- phase 6: hid over own h-half (ctx from SMEM); broadcast to
        //      every CTA's sxAll[jown][h]. ----
        {
            const float4 a4 = ((const float4*)salpha)[lane];
#pragma unroll 2
            for (int rr = warp; rr < 256; rr += NW) {
                const float4 cv = ((const float4*)(sctx + (size_t)rr * LL))[lane];
                float acc = cv.x * a4.x + cv.y * a4.y + cv.z * a4.z + cv.w * a4.w;
                acc = warp_sum(acc);
                const int h = half * 256 + rr;
                if (lane < CR) {
                    float* x = (float*)cluster.map_shared_rank(sxAll, lane);
                    x[jown * 2 * HH + h] = acc;
                }
            }
        }
        cluster.sync();

        // ---- phase 7: h_new.  rank computes Wout rows [rank*64,+64) for all
        //      4 batches; broadcast every value to all 8 CTAs' shAll[j][row]. ----
        {
#pragma unroll 2
            for (int rr = warp; rr < 64; rr += NW) {
                const int row = rank * 64 + rr;
                const float4* wrow = (const float4*)(Wout + (size_t)row * 2 * HH);
                float a0 = 0.f, a1 = 0.f, a2 = 0.f, a3 = 0.f;
#pragma unroll
                for (int t = 0; t < 8; t++) {
                    float4 w  = wrow[t * 32 + lane];
                    float4 x0 = ((const float4*)(sxAll + 0*2*HH))[t * 32 + lane];
                    float4 x1 = ((const float4*)(sxAll + 1*2*HH))[t * 32 + lane];
                    float4 x2 = ((const float4*)(sxAll + 2*2*HH))[t * 32 + lane];
                    float4 x3 = ((const float4*)(sxAll + 3*2*HH))[t * 32 + lane];
                    a0 += w.x*x0.x + w.y*x0.y + w.z*x0.z + w.w*x0.w;
                    a1 += w.x*x1.x + w.y*x1.y + w.z*x1.z + w.w*x1.w;
                    a2 += w.x*x2.x + w.y*x2.y + w.z*x2.z + w.w*x2.w;
                    a3 += w.x*x3.x + w.y*x3.y + w.z*x3.z + w.w*x3.w;
                }
                a0 = warp_sum(a0); a1 = warp_sum(a1);
                a2 = warp_sum(a2); a3 = warp_sum(a3);
                float bb = bout[row];
                {   // 32 lanes = 4 batches x 8 dst ranks, one store each
                    int j   = lane >> 3;      // 0..3
                    int dst = lane & 7;       // 0..7
                    float aj = (j == 0) ? a0 : (j == 1) ? a1 : (j == 2) ? a2 : a3;
                    float v = ftanh(aj + bb);
                    float* hdst = (float*)cluster.map_shared_rank(shAll, dst);
                    hdst[j * HH + row] = v;
                }
            }
        }
        cluster.sync();
    }

    // ---- final h_f, c_f ----
    float* out_hf = out + (size_t)BB * LL * LL + (size_t)BB * LL;
    float* out_cf = out_hf + (size_t)BB * HH;
    if (half == 0)
        for (int i = tid; i < HH; i += NT)
            out_hf[(size_t)b * HH + i] = shAll[jown * HH + i];
    if (tid < 256)
        out_cf[(size_t)b * HH + half * 256 + tid] = sc[tid];
}

// ---------------------------------------------------------------------------
// Launcher.  Input order (metadata):
//  0 embedded_inputs (unused)  1 decoder_input (unused)
//  2 h0  3 c0  4 context  5 W_hh  6 b_hh  7 W_in  8 b_in
//  9 W_ctx  10 b_ctx  11 V  12 W_out  13 b_out
// Output: concat of outputs[B,L,L], pointers[B,L], h_f[B,H], c_f[B,H] (f32)
// ---------------------------------------------------------------------------
extern "C" void kernel_launch(void* const* d_in, const int* in_sizes, int n_in,
                              void* d_out, int out_size)
{
    (void)in_sizes; (void)n_in; (void)out_size;
    const float* h0      = (const float*)d_in[2];
    const float* c0      = (const float*)d_in[3];
    const float* context = (const float*)d_in[4];
    const float* Whh     = (const float*)d_in[5];
    const float* bhh     = (const float*)d_in[6];
    const float* Win     = (const float*)d_in[7];
    const float* bin     = (const float*)d_in[8];
    const float* Wctx    = (const float*)d_in[9];
    const float* bctx    = (const float*)d_in[10];
    const float* V       = (const float*)d_in[11];
    const float* Wout    = (const float*)d_in[12];
    const float* bout    = (const float*)d_in[13];
    float* out = (float*)d_out;

    cudaFuncSetAttribute(ptrnet_kernel,
                         cudaFuncAttributeMaxDynamicSharedMemorySize, SMEM_BYTES);

    ctx_precompute_kernel<<<dim3(BB, HH / 64), 128>>>(context, Wctx, bctx);
    ptrnet_kernel<<<BB * 2, NT, SMEM_BYTES>>>(h0, c0, Whh, bhh, Win, bin, V,
                                              Wout, bout, out);
}